// round 7
// baseline (speedup 1.0000x reference)
#include <cuda_runtime.h>
#include <cuda_bf16.h>
#include <cstdint>
#include <cstddef>

#define HDIM   256
#define WDIM   256
#define C_IN   32
#define KTOT   96
#define WT     64
#define NCHUNK 4
#define SPITCH 68
#define EPITCH 66
#define NTHREADS 512

// ---- smem byte offsets ------------------------------------------------
#define OFF_AFRAG 0                          // [mt16][kt6][split2][lane32][16B] = 98304
#define OFF_BIAS  98304                      // 256 f32
#define OFF_SCR   99328                      // [96][SPITCH] f32 = 26112
#define OFF_BFRAG 125440                     // [split2][kt6][nt8][lane32][8B] = 24576
#define OFF_IB    150016                     // i gates [64][EPITCH] f32
#define OFF_FB    166912
#define OFF_GB    183808
#define OFF_OS    200704                     // 64 f32 sigma(o) at w=255
#define OFF_HS    200960                     // 64 f32 h column
#define SMEM_BYTES 201216

#define AFRAG_OFF(mt,kt,s,lane) (OFF_AFRAG + ((((mt)*6+(kt))*2+(s))*32 + (lane))*16)
#define BFRAG_OFF(s,kt,nt,lane) (OFF_BFRAG + ((((s)*6+(kt))*8+(nt))*32 + (lane))*8)

typedef unsigned int u32;

// ---- activations (validated: rel_err 4.7e-6 end-to-end in R4/R6) ------
static __device__ __forceinline__ float sigmoid_f(float x){
    float e = __expf(-x);
    return __fdividef(1.0f, 1.0f + e);
}
static __device__ __forceinline__ float tanh_f(float x){
    return 1.0f - __fdividef(2.0f, __expf(2.0f * x) + 1.0f);
}

static __device__ __forceinline__ void split_bf16(float v, u32& hi, u32& lo){
    __nv_bfloat16 bh = __float2bfloat16(v);
    float r = v - __bfloat162float(bh);
    __nv_bfloat16 bl = __float2bfloat16(r);
    hi = (u32)__bfloat16_as_ushort(bh);
    lo = (u32)__bfloat16_as_ushort(bl);
}
static __device__ __forceinline__ u32 pack2(u32 lo16, u32 hi16){
    return lo16 | (hi16 << 16);
}

static __device__ __forceinline__ void mma16816(float* c, u32 a0, u32 a1, u32 a2, u32 a3,
                                                u32 b0, u32 b1){
    asm volatile("mma.sync.aligned.m16n8k16.row.col.f32.bf16.bf16.f32 "
                 "{%0,%1,%2,%3}, {%4,%5,%6,%7}, {%8,%9}, {%0,%1,%2,%3};"
                 : "+f"(c[0]), "+f"(c[1]), "+f"(c[2]), "+f"(c[3])
                 : "r"(a0), "r"(a1), "r"(a2), "r"(a3), "r"(b0), "r"(b1));
}

// gate reorder: smem oc' order [i,f,g,o]; reference conv order [i,f,o,g]
static __device__ __forceinline__ int orig_oc(int ocp){
    return (ocp < 128) ? ocp : ((ocp < 192) ? (ocp + 64) : (ocp - 64));
}
// k = kh*32 + c  ->  flat W index offset c*3 + kh
static __device__ __forceinline__ int ck_of(int k){ return (k & 31) * 3 + (k >> 5); }

extern __shared__ char smem[];

__global__ void __launch_bounds__(NTHREADS, 1)
rowlstm_mma(const float* __restrict__ x,
            const float* __restrict__ Wc,
            const float* __restrict__ bc,
            float* __restrict__ out,
            int nrows)
{
    const int tid  = threadIdx.x;
    const int wid  = tid >> 5;     // 0..15
    const int lane = tid & 31;
    const int g    = lane >> 2;
    const int tg   = lane & 3;

    float* bias_s = (float*)(smem + OFF_BIAS);
    float* scr    = (float*)(smem + OFF_SCR);
    float* ib     = (float*)(smem + OFF_IB);
    float* fb     = (float*)(smem + OFF_FB);
    float* gb2    = (float*)(smem + OFF_GB);
    float* o_s    = (float*)(smem + OFF_OS);
    float* h_s    = (float*)(smem + OFF_HS);

    // ================= Phase 0 (once): bias + A fragments (hi/lo bf16) ====
    if (tid < 256) bias_s[tid] = bc[orig_oc(tid)];
    for (int combo = wid; combo < 96; combo += 16){
        const int mt = combo / 6, kt = combo % 6;
        const int r0 = mt * 16 + g;
        const int k0 = kt * 16 + 2 * tg;
        const int o0 = orig_oc(r0), o1 = orig_oc(r0 + 8);
        float f00 = Wc[o0 * KTOT + ck_of(k0)];
        float f01 = Wc[o0 * KTOT + ck_of(k0 + 1)];
        float f02 = Wc[o0 * KTOT + ck_of(k0 + 8)];
        float f03 = Wc[o0 * KTOT + ck_of(k0 + 9)];
        float f10 = Wc[o1 * KTOT + ck_of(k0)];
        float f11 = Wc[o1 * KTOT + ck_of(k0 + 1)];
        float f12 = Wc[o1 * KTOT + ck_of(k0 + 8)];
        float f13 = Wc[o1 * KTOT + ck_of(k0 + 9)];
        u32 h00,l00,h01,l01,h02,l02,h03,l03,h10,l10,h11,l11,h12,l12,h13,l13;
        split_bf16(f00,h00,l00); split_bf16(f01,h01,l01);
        split_bf16(f02,h02,l02); split_bf16(f03,h03,l03);
        split_bf16(f10,h10,l10); split_bf16(f11,h11,l11);
        split_bf16(f12,h12,l12); split_bf16(f13,h13,l13);
        uint4 hi4 = make_uint4(pack2(h00,h01), pack2(h10,h11), pack2(h02,h03), pack2(h12,h13));
        uint4 lo4 = make_uint4(pack2(l00,l01), pack2(l10,l11), pack2(l02,l03), pack2(l12,l13));
        *(uint4*)(smem + AFRAG_OFF(mt,kt,0,lane)) = hi4;
        *(uint4*)(smem + AFRAG_OFF(mt,kt,1,lane)) = lo4;
    }
    __syncthreads();

    // ================= row loop (persistent CTA) ==========================
    for (int row = blockIdx.x; row < nrows; row += gridDim.x){
        const int h = row & (HDIM - 1);
        const int b = row >> 8;
        float creg = 0.0f;                      // cell state (warps 0,1)

        // stage chunk `chunk` into scr with threads [tbase, tbase+nth)
        auto stage = [&](int chunk, int tbase, int nth){
            const int w0g = chunk * WT;
            const int tl = tid - tbase;
            for (int idx = tl; idx < 1536; idx += nth){   // float4 slots
                int r  = idx >> 4;            // 0..95 (k index)
                int c4 = idx & 15;
                int hh = h + (r >> 5) - 1;
                float4 v = make_float4(0.f, 0.f, 0.f, 0.f);
                if (hh >= 0 && hh < HDIM)
                    v = *(const float4*)(x + (((size_t)b * C_IN + (r & 31)) * HDIM + hh) * WDIM + w0g + c4 * 4);
                *(float4*)(scr + r * SPITCH + c4 * 4) = v;
            }
        };

        stage(0, 0, NTHREADS);
        __syncthreads();

        for (int n = 0; n < NCHUNK; n++){
            // ---- build B fragments (hi/lo): warp -> (nt = wid&7, kt-triple = wid>>3)
            {
                const int nt  = wid & 7;
                const int ktb = (wid >> 3) * 3;
                const int w   = nt * 8 + g;
                #pragma unroll
                for (int j = 0; j < 3; j++){
                    const int kt = ktb + j;
                    const int k0 = kt * 16 + 2 * tg;
                    float v00 = scr[k0 * SPITCH + w];
                    float v01 = scr[(k0 + 1) * SPITCH + w];
                    float v10 = scr[(k0 + 8) * SPITCH + w];
                    float v11 = scr[(k0 + 9) * SPITCH + w];
                    u32 hA,lA,hB,lB,hC,lC,hD,lD;
                    split_bf16(v00,hA,lA); split_bf16(v01,hB,lB);
                    split_bf16(v10,hC,lC); split_bf16(v11,hD,lD);
                    *(uint2*)(smem + BFRAG_OFF(0,kt,nt,lane)) = make_uint2(pack2(hA,hB), pack2(hC,hD));
                    *(uint2*)(smem + BFRAG_OFF(1,kt,nt,lane)) = make_uint2(pack2(lA,lB), pack2(lC,lD));
                }
            }
            __syncthreads();   // S2: Bfrag ready

            // ---- MMA: one unit per warp = 3 mt x 2 nt (16 units = 12mt x 8nt)
            {
                const int t  = wid >> 2;        // 0..3 -> mt = 3t..3t+2
                const int nq = wid & 3;         // nt = 2nq, 2nq+1
                float acc[3][2][4];
                #pragma unroll
                for (int m = 0; m < 3; m++)
                    #pragma unroll
                    for (int q = 0; q < 2; q++)
                        acc[m][q][0]=acc[m][q][1]=acc[m][q][2]=acc[m][q][3]=0.f;

                #pragma unroll
                for (int p = 0; p < 3; p++){    // (Ah,Bh),(Al,Bh),(Ah,Bl)
                    const int as = (p == 1) ? 1 : 0;
                    const int bs = (p == 2) ? 1 : 0;
                    #pragma unroll
                    for (int kt = 0; kt < 6; kt++){
                        uint4 a0 = *(const uint4*)(smem + AFRAG_OFF(3*t+0,kt,as,lane));
                        uint4 a1 = *(const uint4*)(smem + AFRAG_OFF(3*t+1,kt,as,lane));
                        uint4 a2 = *(const uint4*)(smem + AFRAG_OFF(3*t+2,kt,as,lane));
                        #pragma unroll
                        for (int q = 0; q < 2; q++){
                            uint2 bv = *(const uint2*)(smem + BFRAG_OFF(bs,kt,2*nq+q,lane));
                            mma16816(acc[0][q], a0.x, a0.y, a0.z, a0.w, bv.x, bv.y);
                            mma16816(acc[1][q], a1.x, a1.y, a1.z, a1.w, bv.x, bv.y);
                            mma16816(acc[2][q], a2.x, a2.y, a2.z, a2.w, bv.x, bv.y);
                        }
                    }
                }

                // ---- fused epilogue: bias + activation + STS.64
                #pragma unroll
                for (int m = 0; m < 3; m++){
                    const int mt   = 3 * t + m;
                    const int gate = mt >> 2;            // 0=i,1=f,2=g
                    const int hidb = (mt & 3) * 16;
                    const float bg0 = bias_s[mt * 16 + g];
                    const float bg1 = bias_s[mt * 16 + g + 8];
                    float* buf = (gate == 0) ? ib : ((gate == 1) ? fb : gb2);
                    #pragma unroll
                    for (int q = 0; q < 2; q++){
                        const int wq = (2 * nq + q) * 8 + 2 * tg;
                        float a0, a1, a2, a3;
                        if (gate < 2){
                            a0 = sigmoid_f(acc[m][q][0] + bg0); a1 = sigmoid_f(acc[m][q][1] + bg0);
                            a2 = sigmoid_f(acc[m][q][2] + bg1); a3 = sigmoid_f(acc[m][q][3] + bg1);
                        } else {
                            a0 = tanh_f(acc[m][q][0] + bg0); a1 = tanh_f(acc[m][q][1] + bg0);
                            a2 = tanh_f(acc[m][q][2] + bg1); a3 = tanh_f(acc[m][q][3] + bg1);
                        }
                        *(float2*)(buf + (hidb + g    ) * EPITCH + wq) = make_float2(a0, a1);
                        *(float2*)(buf + (hidb + g + 8) * EPITCH + wq) = make_float2(a2, a3);
                    }
                }
            }

            // ---- o gate: last chunk only, w=255 (nt=7), warps 3,7,11,15
            if (n == NCHUNK - 1 && (wid & 3) == 3){
                const int mt = 12 + (wid >> 2);
                float acc[4] = {0.f, 0.f, 0.f, 0.f};
                #pragma unroll
                for (int p = 0; p < 3; p++){
                    const int as = (p == 1) ? 1 : 0;
                    const int bs = (p == 2) ? 1 : 0;
                    #pragma unroll
                    for (int kt = 0; kt < 6; kt++){
                        uint4 av = *(const uint4*)(smem + AFRAG_OFF(mt,kt,as,lane));
                        uint2 bv = *(const uint2*)(smem + BFRAG_OFF(bs,kt,7,lane));
                        mma16816(acc, av.x, av.y, av.z, av.w, bv.x, bv.y);
                    }
                }
                if (tg == 3){   // col 2tg+1 = 7 -> local w 63 = global 255
                    const int oc0 = mt * 16 + g;
                    o_s[oc0 - 192]     = sigmoid_f(acc[1] + bias_s[oc0]);
                    o_s[oc0 - 192 + 8] = sigmoid_f(acc[3] + bias_s[oc0 + 8]);
                }
            }
            __syncthreads();   // S3: gates (+ o_s on last chunk) visible

            // ---- parallel tail: warps 0-1 scan chunk n; warps 2-15 stage n+1
            if (wid < 2){
                const int hid = wid * 32 + lane;
                float c = creg;
                #pragma unroll 8
                for (int w = 0; w < WT; w++){
                    float fv = fb [hid * EPITCH + w];
                    float iv = ib [hid * EPITCH + w];
                    float gv = gb2[hid * EPITCH + w];
                    c = fv * c + iv * gv;
                }
                creg = c;
                if (n == NCHUNK - 1)
                    h_s[hid] = o_s[hid] * tanh_f(c);
            } else if (n < NCHUNK - 1){
                stage(n + 1, 64, NTHREADS - 64);
            }
            __syncthreads();   // S1: scr(n+1) ready / h_s ready
        }

        // ---- broadcast write out[b][hid][h][0..255] (512 threads: 8 hid rows/pass)
        {
            const int hq = tid >> 6;   // 0..7
            const int w4 = tid & 63;
            #pragma unroll
            for (int r = 0; r < 8; r++){
                int hid = hq * 8 + r;
                float v = h_s[hid];
                float4 vv = make_float4(v, v, v, v);
                *(float4*)(out + (((size_t)b * 64 + hid) * HDIM + h) * WDIM + w4 * 4) = vv;
            }
        }
        __syncthreads();
    }
}

extern "C" void kernel_launch(void* const* d_in, const int* in_sizes, int n_in,
                              void* d_out, int out_size)
{
    const float* x  = (const float*)d_in[0];
    const float* Wc = (const float*)d_in[1];
    const float* bc = (const float*)d_in[2];
    float* out = (float*)d_out;

    const int B = in_sizes[0] / (C_IN * HDIM * WDIM);
    const int nrows = B * HDIM;

    static bool attr_done = false;
    if (!attr_done){
        cudaFuncSetAttribute(rowlstm_mma,
                             cudaFuncAttributeMaxDynamicSharedMemorySize,
                             SMEM_BYTES);
        attr_done = true;
    }

    int grid = 148;
    if (nrows < grid) grid = nrows;
    rowlstm_mma<<<grid, NTHREADS, SMEM_BYTES>>>(x, Wc, bc, out, nrows);
}

// round 8
// speedup vs baseline: 1.7392x; 1.7392x over previous
#include <cuda_runtime.h>
#include <cuda_bf16.h>
#include <cstdint>
#include <cstddef>

#define HDIM   256
#define WDIM   256
#define C_IN   32
#define KTOT   96
#define WT     64
#define NCHUNK 4
#define SPITCH 68
#define NTHREADS 256

// ---- smem byte offsets ------------------------------------------------
#define OFF_AFRAG 0                          // [mt16][kt6][split2][lane32][16B] = 98304
#define OFF_BIAS  98304                      // 256 f32
#define OFF_SCR   99328                      // [96][SPITCH] f32 = 26112
#define OFF_BFRAG 125440                     // [buf2][split2][kt6][nt8][lane32][8B] = 49152
#define OFF_HS    174592                     // 64 f32 h column
#define SMEM_BYTES 174848

#define AFRAG_OFF(mt,kt,s,lane) (OFF_AFRAG + ((((mt)*6+(kt))*2+(s))*32 + (lane))*16)
#define BOFF(buf,s,kt,nt,lane)  (OFF_BFRAG + (buf)*24576 + ((((s)*6+(kt))*8+(nt))*32 + (lane))*8)

typedef unsigned int u32;

// ---- named split barriers --------------------------------------------
static __device__ __forceinline__ void bar_sync(int id, int cnt){
    asm volatile("bar.sync %0, %1;" :: "r"(id), "r"(cnt) : "memory");
}
static __device__ __forceinline__ void bar_arrive(int id, int cnt){
    asm volatile("bar.arrive %0, %1;" :: "r"(id), "r"(cnt) : "memory");
}

// ---- activations (validated path, rel_err 4.7e-6 in R4/R6) ------------
static __device__ __forceinline__ float sigmoid_f(float x){
    float e = __expf(-x);
    return __fdividef(1.0f, 1.0f + e);
}
static __device__ __forceinline__ float tanh_f(float x){
    return 1.0f - __fdividef(2.0f, __expf(2.0f * x) + 1.0f);
}

static __device__ __forceinline__ void split_bf16(float v, u32& hi, u32& lo){
    __nv_bfloat16 bh = __float2bfloat16(v);
    float r = v - __bfloat162float(bh);
    __nv_bfloat16 bl = __float2bfloat16(r);
    hi = (u32)__bfloat16_as_ushort(bh);
    lo = (u32)__bfloat16_as_ushort(bl);
}
static __device__ __forceinline__ u32 pack2(u32 lo16, u32 hi16){
    return lo16 | (hi16 << 16);
}

static __device__ __forceinline__ void mma16816(float* c, uint4 a, uint2 b){
    asm volatile("mma.sync.aligned.m16n8k16.row.col.f32.bf16.bf16.f32 "
                 "{%0,%1,%2,%3}, {%4,%5,%6,%7}, {%8,%9}, {%0,%1,%2,%3};"
                 : "+f"(c[0]), "+f"(c[1]), "+f"(c[2]), "+f"(c[3])
                 : "r"(a.x), "r"(a.y), "r"(a.z), "r"(a.w), "r"(b.x), "r"(b.y));
}

// gate reorder: smem oc' order [i,f,g,o]; reference conv order [i,f,o,g]
static __device__ __forceinline__ int orig_oc(int ocp){
    return (ocp < 128) ? ocp : ((ocp < 192) ? (ocp + 64) : (ocp - 64));
}
// k = kh*32 + c  ->  flat W index offset c*3 + kh
static __device__ __forceinline__ int ck_of(int k){ return (k & 31) * 3 + (k >> 5); }

extern __shared__ char smem[];

__global__ void __launch_bounds__(NTHREADS, 1)
rowlstm_ws(const float* __restrict__ x,
           const float* __restrict__ Wc,
           const float* __restrict__ bc,
           float* __restrict__ out,
           int nrows)
{
    const int tid  = threadIdx.x;
    const int wid  = tid >> 5;
    const int lane = tid & 31;
    const int g    = lane >> 2;
    const int tg   = lane & 3;

    float* bias_s = (float*)(smem + OFF_BIAS);
    float* scr    = (float*)(smem + OFF_SCR);
    float* h_s    = (float*)(smem + OFF_HS);

    // ================= Phase 0 (once, all warps): bias + A fragments ======
    bias_s[tid] = bc[orig_oc(tid)];
    for (int combo = wid; combo < 96; combo += 8){
        const int mt = combo / 6, kt = combo % 6;
        const int r0 = mt * 16 + g;
        const int k0 = kt * 16 + 2 * tg;
        const int o0 = orig_oc(r0), o1 = orig_oc(r0 + 8);
        float f00 = Wc[o0 * KTOT + ck_of(k0)];
        float f01 = Wc[o0 * KTOT + ck_of(k0 + 1)];
        float f02 = Wc[o0 * KTOT + ck_of(k0 + 8)];
        float f03 = Wc[o0 * KTOT + ck_of(k0 + 9)];
        float f10 = Wc[o1 * KTOT + ck_of(k0)];
        float f11 = Wc[o1 * KTOT + ck_of(k0 + 1)];
        float f12 = Wc[o1 * KTOT + ck_of(k0 + 8)];
        float f13 = Wc[o1 * KTOT + ck_of(k0 + 9)];
        u32 h00,l00,h01,l01,h02,l02,h03,l03,h10,l10,h11,l11,h12,l12,h13,l13;
        split_bf16(f00,h00,l00); split_bf16(f01,h01,l01);
        split_bf16(f02,h02,l02); split_bf16(f03,h03,l03);
        split_bf16(f10,h10,l10); split_bf16(f11,h11,l11);
        split_bf16(f12,h12,l12); split_bf16(f13,h13,l13);
        uint4 hi4 = make_uint4(pack2(h00,h01), pack2(h10,h11), pack2(h02,h03), pack2(h12,h13));
        uint4 lo4 = make_uint4(pack2(l00,l01), pack2(l10,l11), pack2(l02,l03), pack2(l12,l13));
        *(uint4*)(smem + AFRAG_OFF(mt,kt,0,lane)) = hi4;
        *(uint4*)(smem + AFRAG_OFF(mt,kt,1,lane)) = lo4;
    }
    __syncthreads();

    if (wid < 4){
        // =========== A group: MMA + epilogue + register scan + output =====
        const int t = wid;
        const float bi0 = bias_s[t*16 + g],        bi1 = bias_s[t*16 + g + 8];
        const float bf0 = bias_s[64 + t*16 + g],   bf1 = bias_s[64 + t*16 + g + 8];
        const float bg0 = bias_s[128 + t*16 + g],  bg1 = bias_s[128 + t*16 + g + 8];
        const float bo0 = bias_s[192 + t*16 + g],  bo1 = bias_s[192 + t*16 + g + 8];
        int cnt = 0;

        for (int row = blockIdx.x; row < nrows; row += gridDim.x){
            const int h = row & (HDIM - 1);
            const int b = row >> 8;
            float c0 = 0.f, c1 = 0.f;            // cell state (tg==3 lanes)

            for (int n = 0; n < NCHUNK; n++){
                const int p = cnt & 1;
                bar_sync(1 + p, 256);            // wait Bfrag[p] full

                float acc[3][8][4];
                #pragma unroll
                for (int m = 0; m < 3; m++)
                    #pragma unroll
                    for (int q = 0; q < 8; q++)
                        acc[m][q][0]=acc[m][q][1]=acc[m][q][2]=acc[m][q][3]=0.f;
                float oacc[4] = {0.f,0.f,0.f,0.f};

                #pragma unroll
                for (int kt = 0; kt < 6; kt++){
                    uint4 ah[3], al[3]; uint2 bh[8], bl[8];
                    #pragma unroll
                    for (int m = 0; m < 3; m++){
                        const int mt = t + 4*m;   // t, 4+t, 8+t
                        ah[m] = *(const uint4*)(smem + AFRAG_OFF(mt,kt,0,lane));
                        al[m] = *(const uint4*)(smem + AFRAG_OFF(mt,kt,1,lane));
                    }
                    #pragma unroll
                    for (int q = 0; q < 8; q++){
                        bh[q] = *(const uint2*)(smem + BOFF(p,0,kt,q,lane));
                        bl[q] = *(const uint2*)(smem + BOFF(p,1,kt,q,lane));
                    }
                    #pragma unroll
                    for (int q = 0; q < 8; q++)
                        #pragma unroll
                        for (int m = 0; m < 3; m++) mma16816(acc[m][q], ah[m], bh[q]);
                    #pragma unroll
                    for (int q = 0; q < 8; q++)
                        #pragma unroll
                        for (int m = 0; m < 3; m++) mma16816(acc[m][q], al[m], bh[q]);
                    #pragma unroll
                    for (int q = 0; q < 8; q++)
                        #pragma unroll
                        for (int m = 0; m < 3; m++) mma16816(acc[m][q], ah[m], bl[q]);
                }
                if (n == NCHUNK - 1){            // o gate: mt=12+t, nt=7 only
                    #pragma unroll
                    for (int kt = 0; kt < 6; kt++){
                        uint4 aho = *(const uint4*)(smem + AFRAG_OFF(12+t,kt,0,lane));
                        uint4 alo = *(const uint4*)(smem + AFRAG_OFF(12+t,kt,1,lane));
                        uint2 b7h = *(const uint2*)(smem + BOFF(p,0,kt,7,lane));
                        uint2 b7l = *(const uint2*)(smem + BOFF(p,1,kt,7,lane));
                        mma16816(oacc, aho, b7h);
                        mma16816(oacc, alo, b7h);
                        mma16816(oacc, aho, b7l);
                    }
                }
                bar_arrive(3 + p, 256);          // Bfrag[p] free

                // ---- epilogue: activations + segmented scan (w ascending)
                #pragma unroll
                for (int q = 0; q < 8; q++){
                    // row g (hid = 16t+g): cols 2tg, 2tg+1
                    float i0 = sigmoid_f(acc[0][q][0] + bi0), i1 = sigmoid_f(acc[0][q][1] + bi0);
                    float f0 = sigmoid_f(acc[1][q][0] + bf0), f1 = sigmoid_f(acc[1][q][1] + bf0);
                    float g0 = tanh_f   (acc[2][q][0] + bg0), g1 = tanh_f   (acc[2][q][1] + bg0);
                    float P0 = f0 * f1;
                    float S0 = fmaf(f1, i0 * g0, i1 * g1);
                    // row g+8: cols [2],[3]
                    float i2 = sigmoid_f(acc[0][q][2] + bi1), i3 = sigmoid_f(acc[0][q][3] + bi1);
                    float f2 = sigmoid_f(acc[1][q][2] + bf1), f3 = sigmoid_f(acc[1][q][3] + bf1);
                    float g2 = tanh_f   (acc[2][q][2] + bg1), g3 = tanh_f   (acc[2][q][3] + bg1);
                    float P1 = f2 * f3;
                    float S1 = fmaf(f3, i2 * g2, i3 * g3);
                    // Kogge-Stone compose across quad (tg ascending = w ascending)
                    #pragma unroll
                    for (int d = 1; d <= 2; d <<= 1){
                        float Pu0 = __shfl_up_sync(0xffffffffu, P0, d, 4);
                        float Su0 = __shfl_up_sync(0xffffffffu, S0, d, 4);
                        float Pu1 = __shfl_up_sync(0xffffffffu, P1, d, 4);
                        float Su1 = __shfl_up_sync(0xffffffffu, S1, d, 4);
                        if (tg >= d){
                            S0 = fmaf(P0, Su0, S0);  P0 *= Pu0;
                            S1 = fmaf(P1, Su1, S1);  P1 *= Pu1;
                        }
                    }
                    if (tg == 3){                 // full 8-w composition -> apply
                        c0 = fmaf(P0, c0, S0);
                        c1 = fmaf(P1, c1, S1);
                    }
                }
                if (n == NCHUNK - 1 && tg == 3){  // col 7 of nt 7 = w 255
                    float o0 = sigmoid_f(oacc[1] + bo0);
                    float o1 = sigmoid_f(oacc[3] + bo1);
                    h_s[t*16 + g]     = o0 * tanh_f(c0);
                    h_s[t*16 + g + 8] = o1 * tanh_f(c1);
                }
                cnt++;
            }

            bar_sync(7, 128);                    // A-internal: h_s visible
            // broadcast write out[b][hid][h][0..255]  (A's 128 threads)
            #pragma unroll
            for (int j = 0; j < 32; j++){
                int idx = j * 128 + tid;         // 0..4095 float4 slots
                int hid = idx >> 6, w4 = idx & 63;
                float v = h_s[hid];
                float4 vv = make_float4(v, v, v, v);
                *(float4*)(out + (((size_t)b * 64 + hid) * HDIM + h) * WDIM + w4 * 4) = vv;
            }
        }
    } else {
        // =========== B group: stage x + build Bfrag (producer) ============
        const int bw = wid - 4;                  // 0..3 -> nt {bw, bw+4}
        const int tl = tid - 128;                // 0..127
        int cnt = 0;

        for (int row = blockIdx.x; row < nrows; row += gridDim.x){
            const int h = row & (HDIM - 1);
            const int b = row >> 8;

            for (int n = 0; n < NCHUNK; n++){
                const int p = cnt & 1;
                const int w0g = n * WT;

                // ---- stage x chunk -> scr (coalesced float4, halo zero)
                #pragma unroll
                for (int it = 0; it < 12; it++){
                    int idx = tl + it * 128;     // 0..1535 float4 slots
                    int r  = idx >> 4;           // k index 0..95
                    int c4 = idx & 15;
                    int hh = h + (r >> 5) - 1;
                    float4 v = make_float4(0.f, 0.f, 0.f, 0.f);
                    if (hh >= 0 && hh < HDIM)
                        v = *(const float4*)(x + (((size_t)b * C_IN + (r & 31)) * HDIM + hh) * WDIM + w0g + c4 * 4);
                    *(float4*)(scr + r * SPITCH + c4 * 4) = v;
                }
                bar_sync(5, 128);                // B-internal: scr ready
                if (cnt >= 2) bar_sync(3 + p, 256);   // wait Bfrag[p] freed by A

                // ---- build B fragments (hi/lo) for nts {bw, bw+4}
                #pragma unroll
                for (int half = 0; half < 2; half++){
                    const int nt = bw + 4 * half;
                    const int w  = nt * 8 + g;
                    #pragma unroll
                    for (int kt = 0; kt < 6; kt++){
                        const int k0 = kt * 16 + 2 * tg;
                        float v00 = scr[k0 * SPITCH + w];
                        float v01 = scr[(k0 + 1) * SPITCH + w];
                        float v10 = scr[(k0 + 8) * SPITCH + w];
                        float v11 = scr[(k0 + 9) * SPITCH + w];
                        u32 hA,lA,hB,lB,hC,lC,hD,lD;
                        split_bf16(v00,hA,lA); split_bf16(v01,hB,lB);
                        split_bf16(v10,hC,lC); split_bf16(v11,hD,lD);
                        *(uint2*)(smem + BOFF(p,0,kt,nt,lane)) = make_uint2(pack2(hA,hB), pack2(hC,hD));
                        *(uint2*)(smem + BOFF(p,1,kt,nt,lane)) = make_uint2(pack2(lA,lB), pack2(lC,lD));
                    }
                }
                bar_arrive(1 + p, 256);          // Bfrag[p] full
                bar_sync(6, 128);                // B-internal: scr free for next stage
                cnt++;
            }
        }
    }
}

extern "C" void kernel_launch(void* const* d_in, const int* in_sizes, int n_in,
                              void* d_out, int out_size)
{
    const float* x  = (const float*)d_in[0];
    const float* Wc = (const float*)d_in[1];
    const float* bc = (const float*)d_in[2];
    float* out = (float*)d_out;

    const int B = in_sizes[0] / (C_IN * HDIM * WDIM);
    const int nrows = B * HDIM;

    static bool attr_done = false;
    if (!attr_done){
        cudaFuncSetAttribute(rowlstm_ws,
                             cudaFuncAttributeMaxDynamicSharedMemorySize,
                             SMEM_BYTES);
        attr_done = true;
    }

    int grid = 148;
    if (nrows < grid) grid = nrows;
    rowlstm_ws<<<grid, NTHREADS, SMEM_BYTES>>>(x, Wc, bc, out, nrows);
}

// round 10
// speedup vs baseline: 1.8490x; 1.0631x over previous
#include <cuda_runtime.h>
#include <cuda_bf16.h>
#include <cstdint>
#include <cstddef>

#define HDIM   256
#define WDIM   256
#define C_IN   32
#define KTOT   96
#define WT     64
#define NCHUNK 4
#define SPITCH 68
#define NTHREADS 384

// ---- smem byte offsets ------------------------------------------------
#define OFF_AFRAG 0                          // [mt16][kt6][split2][lane32][16B] = 98304
#define OFF_BIAS  98304                      // 256 f32
#define OFF_SCR   99328                      // [96][SPITCH] f32 = 26112
#define OFF_BFRAG 125440                     // [buf2][split2][kt6][nt8][lane32][8B] = 49152
#define OFF_HS    174592                     // 64 f32 h column
#define OFF_OS    174848                     // 64 f32 sigma(o)
#define OFF_SEG   175104                     // [par2][64] float2 = 1024
#define SMEM_BYTES 176128

#define AFRAG_OFF(mt,kt,s,lane) (OFF_AFRAG + ((((mt)*6+(kt))*2+(s))*32 + (lane))*16)
#define BOFF(buf,s,kt,nt,lane)  (OFF_BFRAG + (buf)*24576 + ((((s)*6+(kt))*8+(nt))*32 + (lane))*8)

typedef unsigned int u32;

// ---- named split barriers --------------------------------------------
static __device__ __forceinline__ void bar_sync(int id, int cnt){
    asm volatile("bar.sync %0, %1;" :: "r"(id), "r"(cnt) : "memory");
}
static __device__ __forceinline__ void bar_arrive(int id, int cnt){
    asm volatile("bar.arrive %0, %1;" :: "r"(id), "r"(cnt) : "memory");
}

// ---- activations (validated path, rel_err 4.7e-6) ---------------------
static __device__ __forceinline__ float sigmoid_f(float x){
    float e = __expf(-x);
    return __fdividef(1.0f, 1.0f + e);
}
static __device__ __forceinline__ float tanh_f(float x){
    return 1.0f - __fdividef(2.0f, __expf(2.0f * x) + 1.0f);
}

static __device__ __forceinline__ void split_bf16(float v, u32& hi, u32& lo){
    __nv_bfloat16 bh = __float2bfloat16(v);
    float r = v - __bfloat162float(bh);
    __nv_bfloat16 bl = __float2bfloat16(r);
    hi = (u32)__bfloat16_as_ushort(bh);
    lo = (u32)__bfloat16_as_ushort(bl);
}
static __device__ __forceinline__ u32 pack2(u32 lo16, u32 hi16){
    return lo16 | (hi16 << 16);
}

static __device__ __forceinline__ void mma16816(float* c, uint4 a, uint2 b){
    asm volatile("mma.sync.aligned.m16n8k16.row.col.f32.bf16.bf16.f32 "
                 "{%0,%1,%2,%3}, {%4,%5,%6,%7}, {%8,%9}, {%0,%1,%2,%3};"
                 : "+f"(c[0]), "+f"(c[1]), "+f"(c[2]), "+f"(c[3])
                 : "r"(a.x), "r"(a.y), "r"(a.z), "r"(a.w), "r"(b.x), "r"(b.y));
}

// gate reorder: smem oc' order [i,f,g,o]; reference conv order [i,f,o,g]
static __device__ __forceinline__ int orig_oc(int ocp){
    return (ocp < 128) ? ocp : ((ocp < 192) ? (ocp + 64) : (ocp - 64));
}
// k = kh*32 + c  ->  flat W index offset c*3 + kh
static __device__ __forceinline__ int ck_of(int k){ return (k & 31) * 3 + (k >> 5); }

extern __shared__ char smem[];

__global__ void __launch_bounds__(NTHREADS, 1)
rowlstm_ws2(const float* __restrict__ x,
            const float* __restrict__ Wc,
            const float* __restrict__ bc,
            float* __restrict__ out,
            int nrows)
{
    const int tid  = threadIdx.x;
    const int wid  = tid >> 5;
    const int lane = tid & 31;
    const int g    = lane >> 2;
    const int tg   = lane & 3;

    float*  bias_s = (float*)(smem + OFF_BIAS);
    float*  scr    = (float*)(smem + OFF_SCR);
    float*  h_s    = (float*)(smem + OFF_HS);
    float*  o_s    = (float*)(smem + OFF_OS);
    float2* seg_s  = (float2*)(smem + OFF_SEG);   // [par][hid]

    // ================= Phase 0 (once, all warps): bias + A fragments ======
    if (tid < 256) bias_s[tid] = bc[orig_oc(tid)];
    for (int combo = wid; combo < 96; combo += 12){
        const int mt = combo / 6, kt = combo % 6;
        const int r0 = mt * 16 + g;
        const int k0 = kt * 16 + 2 * tg;
        const int o0 = orig_oc(r0), o1 = orig_oc(r0 + 8);
        float f00 = Wc[o0 * KTOT + ck_of(k0)];
        float f01 = Wc[o0 * KTOT + ck_of(k0 + 1)];
        float f02 = Wc[o0 * KTOT + ck_of(k0 + 8)];
        float f03 = Wc[o0 * KTOT + ck_of(k0 + 9)];
        float f10 = Wc[o1 * KTOT + ck_of(k0)];
        float f11 = Wc[o1 * KTOT + ck_of(k0 + 1)];
        float f12 = Wc[o1 * KTOT + ck_of(k0 + 8)];
        float f13 = Wc[o1 * KTOT + ck_of(k0 + 9)];
        u32 h00,l00,h01,l01,h02,l02,h03,l03,h10,l10,h11,l11,h12,l12,h13,l13;
        split_bf16(f00,h00,l00); split_bf16(f01,h01,l01);
        split_bf16(f02,h02,l02); split_bf16(f03,h03,l03);
        split_bf16(f10,h10,l10); split_bf16(f11,h11,l11);
        split_bf16(f12,h12,l12); split_bf16(f13,h13,l13);
        uint4 hi4 = make_uint4(pack2(h00,h01), pack2(h10,h11), pack2(h02,h03), pack2(h12,h13));
        uint4 lo4 = make_uint4(pack2(l00,l01), pack2(l10,l11), pack2(l02,l03), pack2(l12,l13));
        *(uint4*)(smem + AFRAG_OFF(mt,kt,0,lane)) = hi4;
        *(uint4*)(smem + AFRAG_OFF(mt,kt,1,lane)) = lo4;
    }
    __syncthreads();

    if (wid < 8){
        // =========== A group: 2 warps per SMSP, MMA + epilogue + scan =====
        const int t  = wid >> 1;     // mt group: mt = t, 4+t, 8+t
        const int nh = wid & 1;      // nt = 4nh .. 4nh+3 (w 32*nh .. 32*nh+31)
        const float bi0 = bias_s[t*16 + g],        bi1 = bias_s[t*16 + g + 8];
        const float bf0 = bias_s[64 + t*16 + g],   bf1 = bias_s[64 + t*16 + g + 8];
        const float bg0 = bias_s[128 + t*16 + g],  bg1 = bias_s[128 + t*16 + g + 8];
        const float bo0 = bias_s[192 + t*16 + g],  bo1 = bias_s[192 + t*16 + g + 8];
        const int hid0 = t*16 + g, hid1 = t*16 + g + 8;
        int cnt = 0;

        for (int row = blockIdx.x; row < nrows; row += gridDim.x){
            const int h = row & (HDIM - 1);
            const int b = row >> 8;
            float c0 = 0.f, c1 = 0.f;            // cell state (nh==1, tg==3)

            for (int n = 0; n < NCHUNK; n++){
                const int p = cnt & 1;
                bar_sync(1 + p, NTHREADS);       // Bfrag[p] full

                float acc[3][4][4];
                #pragma unroll
                for (int m = 0; m < 3; m++)
                    #pragma unroll
                    for (int q = 0; q < 4; q++)
                        acc[m][q][0]=acc[m][q][1]=acc[m][q][2]=acc[m][q][3]=0.f;
                float oacc[4] = {0.f,0.f,0.f,0.f};

                #pragma unroll
                for (int kt = 0; kt < 6; kt++){
                    uint4 ah[3], al[3];
                    #pragma unroll
                    for (int m = 0; m < 3; m++){
                        const int mt = t + 4*m;
                        ah[m] = *(const uint4*)(smem + AFRAG_OFF(mt,kt,0,lane));
                        al[m] = *(const uint4*)(smem + AFRAG_OFF(mt,kt,1,lane));
                    }
                    #pragma unroll
                    for (int q = 0; q < 4; q++){
                        const int nt = 4*nh + q;
                        uint2 bh = *(const uint2*)(smem + BOFF(p,0,kt,nt,lane));
                        uint2 bl = *(const uint2*)(smem + BOFF(p,1,kt,nt,lane));
                        #pragma unroll
                        for (int m = 0; m < 3; m++){
                            mma16816(acc[m][q], ah[m], bh);
                            mma16816(acc[m][q], al[m], bh);
                            mma16816(acc[m][q], ah[m], bl);
                        }
                    }
                }
                if (n == NCHUNK - 1 && nh == 0){ // o gate on the idle half
                    #pragma unroll
                    for (int kt = 0; kt < 6; kt++){
                        uint4 aho = *(const uint4*)(smem + AFRAG_OFF(12+t,kt,0,lane));
                        uint4 alo = *(const uint4*)(smem + AFRAG_OFF(12+t,kt,1,lane));
                        uint2 b7h = *(const uint2*)(smem + BOFF(p,0,kt,7,lane));
                        uint2 b7l = *(const uint2*)(smem + BOFF(p,1,kt,7,lane));
                        mma16816(oacc, aho, b7h);
                        mma16816(oacc, alo, b7h);
                        mma16816(oacc, aho, b7l);
                    }
                }
                bar_arrive(3 + p, NTHREADS);     // Bfrag[p] free

                // ---- epilogue: activations + quad scan + segment compose
                float Ps0 = 1.f, Ss0 = 0.f, Ps1 = 1.f, Ss1 = 0.f;
                #pragma unroll
                for (int q = 0; q < 4; q++){
                    float i0 = sigmoid_f(acc[0][q][0] + bi0), i1 = sigmoid_f(acc[0][q][1] + bi0);
                    float f0 = sigmoid_f(acc[1][q][0] + bf0), f1 = sigmoid_f(acc[1][q][1] + bf0);
                    float g0 = tanh_f   (acc[2][q][0] + bg0), g1 = tanh_f   (acc[2][q][1] + bg0);
                    float P0 = f0 * f1;
                    float S0 = fmaf(f1, i0 * g0, i1 * g1);
                    float i2 = sigmoid_f(acc[0][q][2] + bi1), i3 = sigmoid_f(acc[0][q][3] + bi1);
                    float f2 = sigmoid_f(acc[1][q][2] + bf1), f3 = sigmoid_f(acc[1][q][3] + bf1);
                    float g2 = tanh_f   (acc[2][q][2] + bg1), g3 = tanh_f   (acc[2][q][3] + bg1);
                    float P1 = f2 * f3;
                    float S1 = fmaf(f3, i2 * g2, i3 * g3);
                    #pragma unroll
                    for (int d = 1; d <= 2; d <<= 1){
                        float Pu0 = __shfl_up_sync(0xffffffffu, P0, d, 4);
                        float Su0 = __shfl_up_sync(0xffffffffu, S0, d, 4);
                        float Pu1 = __shfl_up_sync(0xffffffffu, P1, d, 4);
                        float Su1 = __shfl_up_sync(0xffffffffu, S1, d, 4);
                        if (tg >= d){
                            S0 = fmaf(P0, Su0, S0);  P0 *= Pu0;
                            S1 = fmaf(P1, Su1, S1);  P1 *= Pu1;
                        }
                    }
                    if (tg == 3){                 // compose octet into segment
                        Ss0 = fmaf(P0, Ss0, S0);  Ps0 *= P0;
                        Ss1 = fmaf(P1, Ss1, S1);  Ps1 *= P1;
                    }
                }
                if (tg == 3){
                    if (nh == 0){                 // publish first-half segment
                        seg_s[p*64 + hid0] = make_float2(Ps0, Ss0);
                        seg_s[p*64 + hid1] = make_float2(Ps1, Ss1);
                        if (n == NCHUNK - 1){     // sigma(o) at w=255
                            o_s[hid0] = sigmoid_f(oacc[1] + bo0);
                            o_s[hid1] = sigmoid_f(oacc[3] + bo1);
                        }
                    }
                }
                bar_sync(7, 256);                // A-internal: segments + o_s
                if (nh == 1 && tg == 3){
                    float2 s0 = seg_s[p*64 + hid0];
                    float2 s1 = seg_s[p*64 + hid1];
                    c0 = fmaf(Ps0, fmaf(s0.x, c0, s0.y), Ss0);
                    c1 = fmaf(Ps1, fmaf(s1.x, c1, s1.y), Ss1);
                    if (n == NCHUNK - 1){
                        h_s[hid0] = o_s[hid0] * tanh_f(c0);
                        h_s[hid1] = o_s[hid1] * tanh_f(c1);
                    }
                }
                cnt++;
            }

            bar_sync(8, 256);                    // h_s visible to all A threads
            // broadcast write out[b][hid][h][0..255]  (256 A threads)
            #pragma unroll
            for (int j = 0; j < 16; j++){
                int idx = j * 256 + tid;         // 0..4095 float4 slots
                int hid = idx >> 6, w4 = idx & 63;
                float v = h_s[hid];
                float4 vv = make_float4(v, v, v, v);
                *(float4*)(out + (((size_t)b * 64 + hid) * HDIM + h) * WDIM + w4 * 4) = vv;
            }
        }
    } else {
        // =========== B group: stage x + build Bfrag (producer) ============
        const int bw = wid - 8;                  // 0..3 -> nt {bw, bw+4}
        const int tl = tid - 256;                // 0..127
        int cnt = 0;

        for (int row = blockIdx.x; row < nrows; row += gridDim.x){
            const int h = row & (HDIM - 1);
            const int b = row >> 8;

            for (int n = 0; n < NCHUNK; n++){
                const int p = cnt & 1;
                const int w0g = n * WT;

                // ---- stage x chunk -> scr (coalesced float4, halo zero)
                #pragma unroll
                for (int it = 0; it < 12; it++){
                    int idx = tl + it * 128;     // 0..1535 float4 slots
                    int r  = idx >> 4;           // k index 0..95
                    int c4 = idx & 15;
                    int hh = h + (r >> 5) - 1;
                    float4 v = make_float4(0.f, 0.f, 0.f, 0.f);
                    if (hh >= 0 && hh < HDIM)
                        v = *(const float4*)(x + (((size_t)b * C_IN + (r & 31)) * HDIM + hh) * WDIM + w0g + c4 * 4);
                    *(float4*)(scr + r * SPITCH + c4 * 4) = v;
                }
                bar_sync(5, 128);                // B-internal: scr ready
                if (cnt >= 2) bar_sync(3 + p, NTHREADS);  // Bfrag[p] freed by A

                // ---- build B fragments (hi/lo) for nts {bw, bw+4}
                #pragma unroll
                for (int half = 0; half < 2; half++){
                    const int nt = bw + 4 * half;
                    const int w  = nt * 8 + g;
                    #pragma unroll
                    for (int kt = 0; kt < 6; kt++){
                        const int k0 = kt * 16 + 2 * tg;
                        float v00 = scr[k0 * SPITCH + w];
                        float v01 = scr[(k0 + 1) * SPITCH + w];
                        float v10 = scr[(k0 + 8) * SPITCH + w];
                        float v11 = scr[(k0 + 9) * SPITCH + w];
                        u32 hA,lA,hB,lB,hC,lC,hD,lD;
                        split_bf16(v00,hA,lA); split_bf16(v01,hB,lB);
                        split_bf16(v10,hC,lC); split_bf16(v11,hD,lD);
                        *(uint2*)(smem + BOFF(p,0,kt,nt,lane)) = make_uint2(pack2(hA,hB), pack2(hC,hD));
                        *(uint2*)(smem + BOFF(p,1,kt,nt,lane)) = make_uint2(pack2(lA,lB), pack2(lC,lD));
                    }
                }
                bar_arrive(1 + p, NTHREADS);     // Bfrag[p] full
                bar_sync(6, 128);                // B-internal: scr free
                cnt++;
            }
        }
    }
}

extern "C" void kernel_launch(void* const* d_in, const int* in_sizes, int n_in,
                              void* d_out, int out_size)
{
    const float* x  = (const float*)d_in[0];
    const float* Wc = (const float*)d_in[1];
    const float* bc = (const float*)d_in[2];
    float* out = (float*)d_out;

    const int B = in_sizes[0] / (C_IN * HDIM * WDIM);
    const int nrows = B * HDIM;

    static bool attr_done = false;
    if (!attr_done){
        cudaFuncSetAttribute(rowlstm_ws2,
                             cudaFuncAttributeMaxDynamicSharedMemorySize,
                             SMEM_BYTES);
        attr_done = true;
    }

    int grid = 148;
    if (nrows < grid) grid = nrows;
    rowlstm_ws2<<<grid, NTHREADS, SMEM_BYTES>>>(x, Wc, bc, out, nrows);
}

// round 12
// speedup vs baseline: 1.8669x; 1.0097x over previous
#include <cuda_runtime.h>
#include <cuda_bf16.h>
#include <cstdint>
#include <cstddef>

#define HDIM   256
#define WDIM   256
#define C_IN   32
#define KTOT   96
#define WT     64
#define NCHUNK 4
#define SPITCH 68
#define NTHREADS 384

// ---- smem byte offsets ------------------------------------------------
#define OFF_AFRAG 0                          // [mt16][kt6][split2][lane32][16B] = 98304
#define OFF_BIAS  98304                      // 256 f32
#define OFF_SCR   99328                      // [96][SPITCH] f32 = 26112
#define OFF_BFRAG 125440                     // [buf2][split2][kt6][nt8][lane32][8B] = 49152
#define OFF_HS    174592                     // 64 f32 h column
#define OFF_OS    174848                     // 64 f32 sigma(o)
#define OFF_SEG   175104                     // [chunk4][half2][hid64] float2 = 4096
#define SMEM_BYTES 179200

#define AFRAG_OFF(mt,kt,s,lane) (OFF_AFRAG + ((((mt)*6+(kt))*2+(s))*32 + (lane))*16)
#define BOFF(buf,s,kt,nt,lane)  (OFF_BFRAG + (buf)*24576 + ((((s)*6+(kt))*8+(nt))*32 + (lane))*8)

typedef unsigned int u32;

// ---- named split barriers --------------------------------------------
static __device__ __forceinline__ void bar_sync(int id, int cnt){
    asm volatile("bar.sync %0, %1;" :: "r"(id), "r"(cnt) : "memory");
}
static __device__ __forceinline__ void bar_arrive(int id, int cnt){
    asm volatile("bar.arrive %0, %1;" :: "r"(id), "r"(cnt) : "memory");
}

// ---- activations (validated path, rel_err 4.7e-6) ---------------------
static __device__ __forceinline__ float sigmoid_f(float x){
    float e = __expf(-x);
    return __fdividef(1.0f, 1.0f + e);
}
static __device__ __forceinline__ float tanh_f(float x){
    return 1.0f - __fdividef(2.0f, __expf(2.0f * x) + 1.0f);
}

static __device__ __forceinline__ void split_bf16(float v, u32& hi, u32& lo){
    __nv_bfloat16 bh = __float2bfloat16(v);
    float r = v - __bfloat162float(bh);
    __nv_bfloat16 bl = __float2bfloat16(r);
    hi = (u32)__bfloat16_as_ushort(bh);
    lo = (u32)__bfloat16_as_ushort(bl);
}
static __device__ __forceinline__ u32 pack2(u32 lo16, u32 hi16){
    return lo16 | (hi16 << 16);
}

static __device__ __forceinline__ void mma16816(float* c, uint4 a, uint2 b){
    asm volatile("mma.sync.aligned.m16n8k16.row.col.f32.bf16.bf16.f32 "
                 "{%0,%1,%2,%3}, {%4,%5,%6,%7}, {%8,%9}, {%0,%1,%2,%3};"
                 : "+f"(c[0]), "+f"(c[1]), "+f"(c[2]), "+f"(c[3])
                 : "r"(a.x), "r"(a.y), "r"(a.z), "r"(a.w), "r"(b.x), "r"(b.y));
}

// gate reorder: smem oc' order [i,f,g,o]; reference conv order [i,f,o,g]
static __device__ __forceinline__ int orig_oc(int ocp){
    return (ocp < 128) ? ocp : ((ocp < 192) ? (ocp + 64) : (ocp - 64));
}
// k = kh*32 + c  ->  flat W index offset c*3 + kh
static __device__ __forceinline__ int ck_of(int k){ return (k & 31) * 3 + (k >> 5); }

extern __shared__ char smem[];

__global__ void __launch_bounds__(NTHREADS, 1)
rowlstm_ws3(const float* __restrict__ x,
            const float* __restrict__ Wc,
            const float* __restrict__ bc,
            float* __restrict__ out,
            int nrows)
{
    const int tid  = threadIdx.x;
    const int wid  = tid >> 5;
    const int lane = tid & 31;
    const int g    = lane >> 2;
    const int tg   = lane & 3;

    float*  bias_s = (float*)(smem + OFF_BIAS);
    float*  scr    = (float*)(smem + OFF_SCR);
    float*  h_s    = (float*)(smem + OFF_HS);
    float*  o_s    = (float*)(smem + OFF_OS);
    float2* seg_s  = (float2*)(smem + OFF_SEG);   // [chunk][half][hid]

    // ================= Phase 0 (once, all warps): bias + A fragments ======
    if (tid < 256) bias_s[tid] = bc[orig_oc(tid)];
    for (int combo = wid; combo < 96; combo += 12){
        const int mt = combo / 6, kt = combo % 6;
        const int r0 = mt * 16 + g;
        const int k0 = kt * 16 + 2 * tg;
        const int o0 = orig_oc(r0), o1 = orig_oc(r0 + 8);
        float f00 = Wc[o0 * KTOT + ck_of(k0)];
        float f01 = Wc[o0 * KTOT + ck_of(k0 + 1)];
        float f02 = Wc[o0 * KTOT + ck_of(k0 + 8)];
        float f03 = Wc[o0 * KTOT + ck_of(k0 + 9)];
        float f10 = Wc[o1 * KTOT + ck_of(k0)];
        float f11 = Wc[o1 * KTOT + ck_of(k0 + 1)];
        float f12 = Wc[o1 * KTOT + ck_of(k0 + 8)];
        float f13 = Wc[o1 * KTOT + ck_of(k0 + 9)];
        u32 h00,l00,h01,l01,h02,l02,h03,l03,h10,l10,h11,l11,h12,l12,h13,l13;
        split_bf16(f00,h00,l00); split_bf16(f01,h01,l01);
        split_bf16(f02,h02,l02); split_bf16(f03,h03,l03);
        split_bf16(f10,h10,l10); split_bf16(f11,h11,l11);
        split_bf16(f12,h12,l12); split_bf16(f13,h13,l13);
        uint4 hi4 = make_uint4(pack2(h00,h01), pack2(h10,h11), pack2(h02,h03), pack2(h12,h13));
        uint4 lo4 = make_uint4(pack2(l00,l01), pack2(l10,l11), pack2(l02,l03), pack2(l12,l13));
        *(uint4*)(smem + AFRAG_OFF(mt,kt,0,lane)) = hi4;
        *(uint4*)(smem + AFRAG_OFF(mt,kt,1,lane)) = lo4;
    }
    __syncthreads();

    if (wid < 8){
        // ===== A group: 2 warps/SMSP, decoupled via deferred composition ==
        const int t  = wid >> 1;     // mt group: mt = t, 4+t, 8+t
        const int nh = wid & 1;      // nt = 4nh .. 4nh+3 (w 32*nh .. 32*nh+31)
        const float bi0 = bias_s[t*16 + g],        bi1 = bias_s[t*16 + g + 8];
        const float bf0 = bias_s[64 + t*16 + g],   bf1 = bias_s[64 + t*16 + g + 8];
        const float bg0 = bias_s[128 + t*16 + g],  bg1 = bias_s[128 + t*16 + g + 8];
        const float bo0 = bias_s[192 + t*16 + g],  bo1 = bias_s[192 + t*16 + g + 8];
        const int hid0 = t*16 + g, hid1 = t*16 + g + 8;
        int cnt = 0;

        for (int row = blockIdx.x; row < nrows; row += gridDim.x){
            const int h = row & (HDIM - 1);
            const int b = row >> 8;

            for (int n = 0; n < NCHUNK; n++){
                const int p = cnt & 1;
                bar_sync(1 + p, NTHREADS);       // Bfrag[p] full

                float acc[3][4][4];
                #pragma unroll
                for (int m = 0; m < 3; m++)
                    #pragma unroll
                    for (int q = 0; q < 4; q++)
                        acc[m][q][0]=acc[m][q][1]=acc[m][q][2]=acc[m][q][3]=0.f;
                float oacc[4] = {0.f,0.f,0.f,0.f};

                #pragma unroll
                for (int kt = 0; kt < 6; kt++){
                    uint4 ah[3], al[3];
                    #pragma unroll
                    for (int m = 0; m < 3; m++){
                        const int mt = t + 4*m;
                        ah[m] = *(const uint4*)(smem + AFRAG_OFF(mt,kt,0,lane));
                        al[m] = *(const uint4*)(smem + AFRAG_OFF(mt,kt,1,lane));
                    }
                    #pragma unroll
                    for (int q = 0; q < 4; q++){
                        const int nt = 4*nh + q;
                        uint2 bh = *(const uint2*)(smem + BOFF(p,0,kt,nt,lane));
                        uint2 bl = *(const uint2*)(smem + BOFF(p,1,kt,nt,lane));
                        #pragma unroll
                        for (int m = 0; m < 3; m++){
                            mma16816(acc[m][q], ah[m], bh);
                            mma16816(acc[m][q], al[m], bh);
                            mma16816(acc[m][q], ah[m], bl);
                        }
                    }
                }
                if (n == NCHUNK - 1 && nh == 0){ // o gate on the first-half warp
                    #pragma unroll
                    for (int kt = 0; kt < 6; kt++){
                        uint4 aho = *(const uint4*)(smem + AFRAG_OFF(12+t,kt,0,lane));
                        uint4 alo = *(const uint4*)(smem + AFRAG_OFF(12+t,kt,1,lane));
                        uint2 b7h = *(const uint2*)(smem + BOFF(p,0,kt,7,lane));
                        uint2 b7l = *(const uint2*)(smem + BOFF(p,1,kt,7,lane));
                        mma16816(oacc, aho, b7h);
                        mma16816(oacc, alo, b7h);
                        mma16816(oacc, aho, b7l);
                    }
                }
                bar_arrive(3 + p, NTHREADS);     // Bfrag[p] free

                // ---- epilogue: activations + quad scan -> one (P,S) per hid
                float Ps0 = 1.f, Ss0 = 0.f, Ps1 = 1.f, Ss1 = 0.f;
                #pragma unroll
                for (int q = 0; q < 4; q++){
                    float i0 = sigmoid_f(acc[0][q][0] + bi0), i1 = sigmoid_f(acc[0][q][1] + bi0);
                    float f0 = sigmoid_f(acc[1][q][0] + bf0), f1 = sigmoid_f(acc[1][q][1] + bf0);
                    float g0 = tanh_f   (acc[2][q][0] + bg0), g1 = tanh_f   (acc[2][q][1] + bg0);
                    float P0 = f0 * f1;
                    float S0 = fmaf(f1, i0 * g0, i1 * g1);
                    float i2 = sigmoid_f(acc[0][q][2] + bi1), i3 = sigmoid_f(acc[0][q][3] + bi1);
                    float f2 = sigmoid_f(acc[1][q][2] + bf1), f3 = sigmoid_f(acc[1][q][3] + bf1);
                    float g2 = tanh_f   (acc[2][q][2] + bg1), g3 = tanh_f   (acc[2][q][3] + bg1);
                    float P1 = f2 * f3;
                    float S1 = fmaf(f3, i2 * g2, i3 * g3);
                    #pragma unroll
                    for (int d = 1; d <= 2; d <<= 1){
                        float Pu0 = __shfl_up_sync(0xffffffffu, P0, d, 4);
                        float Su0 = __shfl_up_sync(0xffffffffu, S0, d, 4);
                        float Pu1 = __shfl_up_sync(0xffffffffu, P1, d, 4);
                        float Su1 = __shfl_up_sync(0xffffffffu, S1, d, 4);
                        if (tg >= d){
                            S0 = fmaf(P0, Su0, S0);  P0 *= Pu0;
                            S1 = fmaf(P1, Su1, S1);  P1 *= Pu1;
                        }
                    }
                    if (tg == 3){                 // compose octet into segment
                        Ss0 = fmaf(P0, Ss0, S0);  Ps0 *= P0;
                        Ss1 = fmaf(P1, Ss1, S1);  Ps1 *= P1;
                    }
                }
                if (tg == 3){                     // publish segment (deferred compose)
                    seg_s[(n*2 + nh)*64 + hid0] = make_float2(Ps0, Ss0);
                    seg_s[(n*2 + nh)*64 + hid1] = make_float2(Ps1, Ss1);
                    if (n == NCHUNK - 1 && nh == 0){   // sigma(o) at w=255
                        o_s[hid0] = sigmoid_f(oacc[1] + bo0);
                        o_s[hid1] = sigmoid_f(oacc[3] + bo1);
                    }
                }
                cnt++;
            }

            // ---- row tail: fold 8 segments in w order, then write h
            bar_sync(7, 256);                    // all segments + o_s visible
            if (tid < 64){
                const int hid = tid;
                float c = 0.f;
                #pragma unroll
                for (int s = 0; s < 2*NCHUNK; s++){
                    float2 ps = seg_s[s*64 + hid];
                    c = fmaf(ps.x, c, ps.y);
                }
                h_s[hid] = o_s[hid] * tanh_f(c);
            }
            bar_sync(8, 256);                    // h_s visible to all A threads
            // broadcast write out[b][hid][h][0..255]  (256 A threads)
            #pragma unroll
            for (int j = 0; j < 16; j++){
                int idx = j * 256 + tid;         // 0..4095 float4 slots
                int hid = idx >> 6, w4 = idx & 63;
                float v = h_s[hid];
                float4 vv = make_float4(v, v, v, v);
                *(float4*)(out + (((size_t)b * 64 + hid) * HDIM + h) * WDIM + w4 * 4) = vv;
            }
        }
    } else {
        // =========== B group: stage x + build Bfrag (producer) ============
        const int bw = wid - 8;                  // 0..3 -> nt {bw, bw+4}
        const int tl = tid - 256;                // 0..127
        int cnt = 0;

        for (int row = blockIdx.x; row < nrows; row += gridDim.x){
            const int h = row & (HDIM - 1);
            const int b = row >> 8;

            for (int n = 0; n < NCHUNK; n++){
                const int p = cnt & 1;
                const int w0g = n * WT;

                // ---- stage x chunk -> scr (coalesced float4, halo zero)
                #pragma unroll
                for (int it = 0; it < 12; it++){
                    int idx = tl + it * 128;     // 0..1535 float4 slots
                    int r  = idx >> 4;           // k index 0..95
                    int c4 = idx & 15;
                    int hh = h + (r >> 5) - 1;
                    float4 v = make_float4(0.f, 0.f, 0.f, 0.f);
                    if (hh >= 0 && hh < HDIM)
                        v = *(const float4*)(x + (((size_t)b * C_IN + (r & 31)) * HDIM + hh) * WDIM + w0g + c4 * 4);
                    *(float4*)(scr + r * SPITCH + c4 * 4) = v;
                }
                bar_sync(5, 128);                // B-internal: scr ready
                if (cnt >= 2) bar_sync(3 + p, NTHREADS);  // Bfrag[p] freed by A

                // ---- build B fragments (hi/lo) for nts {bw, bw+4}
                #pragma unroll
                for (int half = 0; half < 2; half++){
                    const int nt = bw + 4 * half;
                    const int w  = nt * 8 + g;
                    #pragma unroll
                    for (int kt = 0; kt < 6; kt++){
                        const int k0 = kt * 16 + 2 * tg;
                        float v00 = scr[k0 * SPITCH + w];
                        float v01 = scr[(k0 + 1) * SPITCH + w];
                        float v10 = scr[(k0 + 8) * SPITCH + w];
                        float v11 = scr[(k0 + 9) * SPITCH + w];
                        u32 hA,lA,hB,lB,hC,lC,hD,lD;
                        split_bf16(v00,hA,lA); split_bf16(v01,hB,lB);
                        split_bf16(v10,hC,lC); split_bf16(v11,hD,lD);
                        *(uint2*)(smem + BOFF(p,0,kt,nt,lane)) = make_uint2(pack2(hA,hB), pack2(hC,hD));
                        *(uint2*)(smem + BOFF(p,1,kt,nt,lane)) = make_uint2(pack2(lA,lB), pack2(lC,lD));
                    }
                }
                bar_arrive(1 + p, NTHREADS);     // Bfrag[p] full
                bar_sync(6, 128);                // B-internal: scr free
                cnt++;
            }
        }
    }
}

extern "C" void kernel_launch(void* const* d_in, const int* in_sizes, int n_in,
                              void* d_out, int out_size)
{
    const float* x  = (const float*)d_in[0];
    const float* Wc = (const float*)d_in[1];
    const float* bc = (const float*)d_in[2];
    float* out = (float*)d_out;

    const int B = in_sizes[0] / (C_IN * HDIM * WDIM);
    const int nrows = B * HDIM;

    static bool attr_done = false;
    if (!attr_done){
        cudaFuncSetAttribute(rowlstm_ws3,
                             cudaFuncAttributeMaxDynamicSharedMemorySize,
                             SMEM_BYTES);
        attr_done = true;
    }

    int grid = 148;
    if (nrows < grid) grid = nrows;
    rowlstm_ws3<<<grid, NTHREADS, SMEM_BYTES>>>(x, Wc, bc, out, nrows);
}

// round 14
// speedup vs baseline: 2.1891x; 1.1726x over previous
#include <cuda_runtime.h>
#include <cuda_bf16.h>
#include <cstdint>
#include <cstddef>

#define HDIM   256
#define WDIM   256
#define C_IN   32
#define KTOT   96
#define WT     64
#define NCHUNK 4
#define SPITCH 68
#define NTHREADS 384

// ---- smem byte offsets ------------------------------------------------
#define OFF_AFRAG 0                          // [mt16][kt6][split2][lane32][16B] = 98304
#define OFF_BIAS  98304                      // 256 f32
#define OFF_SCR   99328                      // [96][SPITCH] f32 = 26112
#define OFF_BFRAG 125440                     // [buf2][split2][kt6][nt8][lane32][8B] = 49152
#define OFF_HS    174592                     // 64 f32 h column
#define OFF_OS    174848                     // 64 f32 sigma(o)
#define OFF_SEG   175104                     // [chunk4][half2][hid64] float2 = 4096
#define SMEM_BYTES 179200

#define AFRAG_OFF(mt,kt,s,lane) (OFF_AFRAG + ((((mt)*6+(kt))*2+(s))*32 + (lane))*16)
#define BOFF(buf,s,kt,nt,lane)  (OFF_BFRAG + (buf)*24576 + ((((s)*6+(kt))*8+(nt))*32 + (lane))*8)

typedef unsigned int u32;

// ---- named split barriers --------------------------------------------
// F0: 1,2   E0: 3,4   B-int: 5,6   A-int: 7,8   F1: 9,10   E1: 11,12
static __device__ __forceinline__ void bar_sync(int id, int cnt){
    asm volatile("bar.sync %0, %1;" :: "r"(id), "r"(cnt) : "memory");
}
static __device__ __forceinline__ void bar_arrive(int id, int cnt){
    asm volatile("bar.arrive %0, %1;" :: "r"(id), "r"(cnt) : "memory");
}

// ---- activations: single-MUFU tanh.approx path ------------------------
static __device__ __forceinline__ float tanh_fast(float x){
    float y;
    asm("tanh.approx.f32 %0, %1;" : "=f"(y) : "f"(x));
    return y;
}
static __device__ __forceinline__ float sigmoid_f(float x){
    return fmaf(tanh_fast(0.5f * x), 0.5f, 0.5f);
}
static __device__ __forceinline__ float tanh_f(float x){
    return tanh_fast(x);
}

static __device__ __forceinline__ void split_bf16(float v, u32& hi, u32& lo){
    __nv_bfloat16 bh = __float2bfloat16(v);
    float r = v - __bfloat162float(bh);
    __nv_bfloat16 bl = __float2bfloat16(r);
    hi = (u32)__bfloat16_as_ushort(bh);
    lo = (u32)__bfloat16_as_ushort(bl);
}
static __device__ __forceinline__ u32 pack2(u32 lo16, u32 hi16){
    return lo16 | (hi16 << 16);
}

static __device__ __forceinline__ void mma16816(float* c, uint4 a, uint2 b){
    asm volatile("mma.sync.aligned.m16n8k16.row.col.f32.bf16.bf16.f32 "
                 "{%0,%1,%2,%3}, {%4,%5,%6,%7}, {%8,%9}, {%0,%1,%2,%3};"
                 : "+f"(c[0]), "+f"(c[1]), "+f"(c[2]), "+f"(c[3])
                 : "r"(a.x), "r"(a.y), "r"(a.z), "r"(a.w), "r"(b.x), "r"(b.y));
}

// gate reorder: smem oc' order [i,f,g,o]; reference conv order [i,f,o,g]
static __device__ __forceinline__ int orig_oc(int ocp){
    return (ocp < 128) ? ocp : ((ocp < 192) ? (ocp + 64) : (ocp - 64));
}
// k = kh*32 + c  ->  flat W index offset c*3 + kh
static __device__ __forceinline__ int ck_of(int k){ return (k & 31) * 3 + (k >> 5); }

extern __shared__ char smem[];

__global__ void __launch_bounds__(NTHREADS, 1)
rowlstm_ws4(const float* __restrict__ x,
            const float* __restrict__ Wc,
            const float* __restrict__ bc,
            float* __restrict__ out,
            int nrows)
{
    const int tid  = threadIdx.x;
    const int wid  = tid >> 5;
    const int lane = tid & 31;
    const int g    = lane >> 2;
    const int tg   = lane & 3;

    float*  bias_s = (float*)(smem + OFF_BIAS);
    float*  scr    = (float*)(smem + OFF_SCR);
    float*  h_s    = (float*)(smem + OFF_HS);
    float*  o_s    = (float*)(smem + OFF_OS);
    float2* seg_s  = (float2*)(smem + OFF_SEG);   // [chunk][half][hid]

    // ================= Phase 0 (once, all warps): bias + A fragments ======
    if (tid < 256) bias_s[tid] = bc[orig_oc(tid)];
    for (int combo = wid; combo < 96; combo += 12){
        const int mt = combo / 6, kt = combo % 6;
        const int r0 = mt * 16 + g;
        const int k0 = kt * 16 + 2 * tg;
        const int o0 = orig_oc(r0), o1 = orig_oc(r0 + 8);
        float f00 = Wc[o0 * KTOT + ck_of(k0)];
        float f01 = Wc[o0 * KTOT + ck_of(k0 + 1)];
        float f02 = Wc[o0 * KTOT + ck_of(k0 + 8)];
        float f03 = Wc[o0 * KTOT + ck_of(k0 + 9)];
        float f10 = Wc[o1 * KTOT + ck_of(k0)];
        float f11 = Wc[o1 * KTOT + ck_of(k0 + 1)];
        float f12 = Wc[o1 * KTOT + ck_of(k0 + 8)];
        float f13 = Wc[o1 * KTOT + ck_of(k0 + 9)];
        u32 h00,l00,h01,l01,h02,l02,h03,l03,h10,l10,h11,l11,h12,l12,h13,l13;
        split_bf16(f00,h00,l00); split_bf16(f01,h01,l01);
        split_bf16(f02,h02,l02); split_bf16(f03,h03,l03);
        split_bf16(f10,h10,l10); split_bf16(f11,h11,l11);
        split_bf16(f12,h12,l12); split_bf16(f13,h13,l13);
        uint4 hi4 = make_uint4(pack2(h00,h01), pack2(h10,h11), pack2(h02,h03), pack2(h12,h13));
        uint4 lo4 = make_uint4(pack2(l00,l01), pack2(l10,l11), pack2(l02,l03), pack2(l12,l13));
        *(uint4*)(smem + AFRAG_OFF(mt,kt,0,lane)) = hi4;
        *(uint4*)(smem + AFRAG_OFF(mt,kt,1,lane)) = lo4;
    }
    __syncthreads();

    if (wid < 8){
        // ===== A group: 2 warps/SMSP, per-half staggered handshake ========
        const int t  = wid >> 1;     // mt group: mt = t, 4+t, 8+t
        const int nh = wid & 1;      // nt = 4nh .. 4nh+3 (w 32*nh .. 32*nh+31)
        const int fb = nh ? 9 : 1;   // full barrier base for my half
        const int eb = nh ? 11 : 3;  // free barrier base for my half
        const float bi0 = bias_s[t*16 + g],        bi1 = bias_s[t*16 + g + 8];
        const float bf0 = bias_s[64 + t*16 + g],   bf1 = bias_s[64 + t*16 + g + 8];
        const float bg0 = bias_s[128 + t*16 + g],  bg1 = bias_s[128 + t*16 + g + 8];
        const float bo0 = bias_s[192 + t*16 + g],  bo1 = bias_s[192 + t*16 + g + 8];
        const int hid0 = t*16 + g, hid1 = t*16 + g + 8;
        int cnt = 0;

        for (int row = blockIdx.x; row < nrows; row += gridDim.x){
            const int h = row & (HDIM - 1);
            const int b = row >> 8;

            for (int n = 0; n < NCHUNK; n++){
                const int p = cnt & 1;
                bar_sync(fb + p, 256);           // my half of Bfrag[p] full

                float acc[3][4][4];
                #pragma unroll
                for (int m = 0; m < 3; m++)
                    #pragma unroll
                    for (int q = 0; q < 4; q++)
                        acc[m][q][0]=acc[m][q][1]=acc[m][q][2]=acc[m][q][3]=0.f;
                float oacc[4] = {0.f,0.f,0.f,0.f};

                #pragma unroll
                for (int kt = 0; kt < 6; kt++){
                    uint4 ah[3], al[3];
                    #pragma unroll
                    for (int m = 0; m < 3; m++){
                        const int mt = t + 4*m;
                        ah[m] = *(const uint4*)(smem + AFRAG_OFF(mt,kt,0,lane));
                        al[m] = *(const uint4*)(smem + AFRAG_OFF(mt,kt,1,lane));
                    }
                    #pragma unroll
                    for (int q = 0; q < 4; q++){
                        const int nt = 4*nh + q;
                        uint2 bh = *(const uint2*)(smem + BOFF(p,0,kt,nt,lane));
                        uint2 bl = *(const uint2*)(smem + BOFF(p,1,kt,nt,lane));
                        #pragma unroll
                        for (int m = 0; m < 3; m++){
                            mma16816(acc[m][q], ah[m], bh);
                            mma16816(acc[m][q], al[m], bh);
                            mma16816(acc[m][q], ah[m], bl);
                        }
                    }
                }
                if (n == NCHUNK - 1 && nh == 1){ // o gate: nt=7 lives in my half
                    #pragma unroll
                    for (int kt = 0; kt < 6; kt++){
                        uint4 aho = *(const uint4*)(smem + AFRAG_OFF(12+t,kt,0,lane));
                        uint4 alo = *(const uint4*)(smem + AFRAG_OFF(12+t,kt,1,lane));
                        uint2 b7h = *(const uint2*)(smem + BOFF(p,0,kt,7,lane));
                        uint2 b7l = *(const uint2*)(smem + BOFF(p,1,kt,7,lane));
                        mma16816(oacc, aho, b7h);
                        mma16816(oacc, alo, b7h);
                        mma16816(oacc, aho, b7l);
                    }
                }
                bar_arrive(eb + p, 256);         // my half of Bfrag[p] free

                // ---- epilogue: activations + quad scan -> one (P,S) per hid
                float Ps0 = 1.f, Ss0 = 0.f, Ps1 = 1.f, Ss1 = 0.f;
                #pragma unroll
                for (int q = 0; q < 4; q++){
                    float i0 = sigmoid_f(acc[0][q][0] + bi0), i1 = sigmoid_f(acc[0][q][1] + bi0);
                    float f0 = sigmoid_f(acc[1][q][0] + bf0), f1 = sigmoid_f(acc[1][q][1] + bf0);
                    float g0 = tanh_f   (acc[2][q][0] + bg0), g1 = tanh_f   (acc[2][q][1] + bg0);
                    float P0 = f0 * f1;
                    float S0 = fmaf(f1, i0 * g0, i1 * g1);
                    float i2 = sigmoid_f(acc[0][q][2] + bi1), i3 = sigmoid_f(acc[0][q][3] + bi1);
                    float f2 = sigmoid_f(acc[1][q][2] + bf1), f3 = sigmoid_f(acc[1][q][3] + bf1);
                    float g2 = tanh_f   (acc[2][q][2] + bg1), g3 = tanh_f   (acc[2][q][3] + bg1);
                    float P1 = f2 * f3;
                    float S1 = fmaf(f3, i2 * g2, i3 * g3);
                    #pragma unroll
                    for (int d = 1; d <= 2; d <<= 1){
                        float Pu0 = __shfl_up_sync(0xffffffffu, P0, d, 4);
                        float Su0 = __shfl_up_sync(0xffffffffu, S0, d, 4);
                        float Pu1 = __shfl_up_sync(0xffffffffu, P1, d, 4);
                        float Su1 = __shfl_up_sync(0xffffffffu, S1, d, 4);
                        if (tg >= d){
                            S0 = fmaf(P0, Su0, S0);  P0 *= Pu0;
                            S1 = fmaf(P1, Su1, S1);  P1 *= Pu1;
                        }
                    }
                    if (tg == 3){                 // compose octet into segment
                        Ss0 = fmaf(P0, Ss0, S0);  Ps0 *= P0;
                        Ss1 = fmaf(P1, Ss1, S1);  Ps1 *= P1;
                    }
                }
                if (tg == 3){                     // publish segment (deferred compose)
                    seg_s[(n*2 + nh)*64 + hid0] = make_float2(Ps0, Ss0);
                    seg_s[(n*2 + nh)*64 + hid1] = make_float2(Ps1, Ss1);
                    if (n == NCHUNK - 1 && nh == 1){   // sigma(o) at w=255
                        o_s[hid0] = sigmoid_f(oacc[1] + bo0);
                        o_s[hid1] = sigmoid_f(oacc[3] + bo1);
                    }
                }
                cnt++;
            }

            // ---- row tail: fold 8 segments in w order, then write h
            bar_sync(7, 256);                    // all segments + o_s visible
            if (tid < 64){
                const int hid = tid;
                float c = 0.f;
                #pragma unroll
                for (int s = 0; s < 2*NCHUNK; s++){
                    float2 ps = seg_s[s*64 + hid];
                    c = fmaf(ps.x, c, ps.y);
                }
                h_s[hid] = o_s[hid] * tanh_f(c);
            }
            bar_sync(8, 256);                    // h_s visible to all A threads
            // broadcast write out[b][hid][h][0..255]  (256 A threads)
            #pragma unroll
            for (int j = 0; j < 16; j++){
                int idx = j * 256 + tid;         // 0..4095 float4 slots
                int hid = idx >> 6, w4 = idx & 63;
                float v = h_s[hid];
                float4 vv = make_float4(v, v, v, v);
                *(float4*)(out + (((size_t)b * 64 + hid) * HDIM + h) * WDIM + w4 * 4) = vv;
            }
        }
    } else {
        // ==== B group: stage x + build Bfrag half0 then half1 (producer) ==
        const int bw = wid - 8;                  // 0..3 -> nt bw (half0), bw+4 (half1)
        const int tl = tid - 256;                // 0..127
        int cnt = 0;

        for (int row = blockIdx.x; row < nrows; row += gridDim.x){
            const int h = row & (HDIM - 1);
            const int b = row >> 8;

            for (int n = 0; n < NCHUNK; n++){
                const int p = cnt & 1;
                const int w0g = n * WT;

                // ---- stage x chunk -> scr (coalesced float4, halo zero)
                #pragma unroll
                for (int it = 0; it < 12; it++){
                    int idx = tl + it * 128;     // 0..1535 float4 slots
                    int r  = idx >> 4;           // k index 0..95
                    int c4 = idx & 15;
                    int hh = h + (r >> 5) - 1;
                    float4 v = make_float4(0.f, 0.f, 0.f, 0.f);
                    if (hh >= 0 && hh < HDIM)
                        v = *(const float4*)(x + (((size_t)b * C_IN + (r & 31)) * HDIM + hh) * WDIM + w0g + c4 * 4);
                    *(float4*)(scr + r * SPITCH + c4 * 4) = v;
                }
                bar_sync(5, 128);                // B-internal: scr ready

                // ---- half 0 (nt = bw)
                if (cnt >= 2) bar_sync(3 + p, 256);   // E0[p]: freed by A nh=0
                {
                    const int nt = bw;
                    const int w  = nt * 8 + g;
                    #pragma unroll
                    for (int kt = 0; kt < 6; kt++){
                        const int k0 = kt * 16 + 2 * tg;
                        float v00 = scr[k0 * SPITCH + w];
                        float v01 = scr[(k0 + 1) * SPITCH + w];
                        float v10 = scr[(k0 + 8) * SPITCH + w];
                        float v11 = scr[(k0 + 9) * SPITCH + w];
                        u32 hA,lA,hB,lB,hC,lC,hD,lD;
                        split_bf16(v00,hA,lA); split_bf16(v01,hB,lB);
                        split_bf16(v10,hC,lC); split_bf16(v11,hD,lD);
                        *(uint2*)(smem + BOFF(p,0,kt,nt,lane)) = make_uint2(pack2(hA,hB), pack2(hC,hD));
                        *(uint2*)(smem + BOFF(p,1,kt,nt,lane)) = make_uint2(pack2(lA,lB), pack2(lC,lD));
                    }
                }
                bar_arrive(1 + p, 256);          // F0[p] full

                // ---- half 1 (nt = bw+4)
                if (cnt >= 2) bar_sync(11 + p, 256);  // E1[p]: freed by A nh=1
                {
                    const int nt = bw + 4;
                    const int w  = nt * 8 + g;
                    #pragma unroll
                    for (int kt = 0; kt < 6; kt++){
                        const int k0 = kt * 16 + 2 * tg;
                        float v00 = scr[k0 * SPITCH + w];
                        float v01 = scr[(k0 + 1) * SPITCH + w];
                        float v10 = scr[(k0 + 8) * SPITCH + w];
                        float v11 = scr[(k0 + 9) * SPITCH + w];
                        u32 hA,lA,hB,lB,hC,lC,hD,lD;
                        split_bf16(v00,hA,lA); split_bf16(v01,hB,lB);
                        split_bf16(v10,hC,lC); split_bf16(v11,hD,lD);
                        *(uint2*)(smem + BOFF(p,0,kt,nt,lane)) = make_uint2(pack2(hA,hB), pack2(hC,hD));
                        *(uint2*)(smem + BOFF(p,1,kt,nt,lane)) = make_uint2(pack2(lA,lB), pack2(lC,lD));
                    }
                }
                bar_arrive(9 + p, 256);          // F1[p] full
                bar_sync(6, 128);                // B-internal: scr free
                cnt++;
            }
        }
    }
}

extern "C" void kernel_launch(void* const* d_in, const int* in_sizes, int n_in,
                              void* d_out, int out_size)
{
    const float* x  = (const float*)d_in[0];
    const float* Wc = (const float*)d_in[1];
    const float* bc = (const float*)d_in[2];
    float* out = (float*)d_out;

    const int B = in_sizes[0] / (C_IN * HDIM * WDIM);
    const int nrows = B * HDIM;

    static bool attr_done = false;
    if (!attr_done){
        cudaFuncSetAttribute(rowlstm_ws4,
                             cudaFuncAttributeMaxDynamicSharedMemorySize,
                             SMEM_BYTES);
        attr_done = true;
    }

    int grid = 148;
    if (nrows < grid) grid = nrows;
    rowlstm_ws4<<<grid, NTHREADS, SMEM_BYTES>>>(x, Wc, bc, out, nrows);
}

// round 17
// speedup vs baseline: 2.6035x; 1.1893x over previous
#include <cuda_runtime.h>
#include <cuda_bf16.h>
#include <cstdint>
#include <cstddef>

#define HDIM   256
#define WDIM   256
#define C_IN   32
#define KTOT   96
#define WT     64
#define NCHUNK 4
#define SPITCH 68
#define NTHREADS 384

// ---- smem byte offsets ------------------------------------------------
#define OFF_AFRAG 0                          // [mt16][kt12][lane32][16B] = 98304
#define OFF_BIAS  98304                      // 256 f32
#define OFF_SCR   99328                      // [96][SPITCH] f32 = 26112
#define OFF_BFRAG 125440                     // [buf2][kt12][nt8][lane32][8B] = 49152
#define OFF_HS    174592                     // 64 f32 h column
#define OFF_OS    174848                     // 64 f32 sigma(o)
#define OFF_SEG   175104                     // [chunk4][half2][hid64] float2 = 4096
#define SMEM_BYTES 179200

#define AFRAG_OFF(mt,kt,lane) (OFF_AFRAG + (((mt)*12+(kt))*32 + (lane))*16)
#define BOFF(buf,kt,nt,lane)  (OFF_BFRAG + (buf)*24576 + (((kt)*8+(nt))*32 + (lane))*8)

typedef unsigned int u32;

// ---- named split barriers --------------------------------------------
// F0: 1,2   E0: 3,4   B-int: 5,6   A-int: 7,8   F1: 9,10   E1: 11,12
static __device__ __forceinline__ void bar_sync(int id, int cnt){
    asm volatile("bar.sync %0, %1;" :: "r"(id), "r"(cnt) : "memory");
}
static __device__ __forceinline__ void bar_arrive(int id, int cnt){
    asm volatile("bar.arrive %0, %1;" :: "r"(id), "r"(cnt) : "memory");
}

// ---- activations: single-MUFU tanh.approx path (validated R14) --------
static __device__ __forceinline__ float tanh_fast(float x){
    float y;
    asm("tanh.approx.f32 %0, %1;" : "=f"(y) : "f"(x));
    return y;
}
static __device__ __forceinline__ float sigmoid_f(float x){
    return fmaf(tanh_fast(0.5f * x), 0.5f, 0.5f);
}
static __device__ __forceinline__ float tanh_f(float x){
    return tanh_fast(x);
}

static __device__ __forceinline__ u32 to_tf32(float f){
    u32 r;
    asm("cvt.rna.tf32.f32 %0, %1;" : "=r"(r) : "f"(f));
    return r;
}

// mma m16n8k8 tf32: D layout identical to m16n8k16 (c0..c3 = rows g/g+8, cols 2tg/2tg+1)
static __device__ __forceinline__ void mma1688(float* c, uint4 a, uint2 b){
    asm volatile("mma.sync.aligned.m16n8k8.row.col.f32.tf32.tf32.f32 "
                 "{%0,%1,%2,%3}, {%4,%5,%6,%7}, {%8,%9}, {%0,%1,%2,%3};"
                 : "+f"(c[0]), "+f"(c[1]), "+f"(c[2]), "+f"(c[3])
                 : "r"(a.x), "r"(a.y), "r"(a.z), "r"(a.w), "r"(b.x), "r"(b.y));
}

// gate reorder: smem oc' order [i,f,g,o]; reference conv order [i,f,o,g]
static __device__ __forceinline__ int orig_oc(int ocp){
    return (ocp < 128) ? ocp : ((ocp < 192) ? (ocp + 64) : (ocp - 64));
}
// k = kh*32 + c  ->  flat W index offset c*3 + kh
static __device__ __forceinline__ int ck_of(int k){ return (k & 31) * 3 + (k >> 5); }

extern __shared__ char smem[];

__global__ void __launch_bounds__(NTHREADS, 1)
rowlstm_tf32(const float* __restrict__ x,
             const float* __restrict__ Wc,
             const float* __restrict__ bc,
             float* __restrict__ out,
             int nrows)
{
    const int tid  = threadIdx.x;
    const int wid  = tid >> 5;
    const int lane = tid & 31;
    const int g    = lane >> 2;
    const int tg   = lane & 3;

    float*  bias_s = (float*)(smem + OFF_BIAS);
    float*  scr    = (float*)(smem + OFF_SCR);
    float*  h_s    = (float*)(smem + OFF_HS);
    float*  o_s    = (float*)(smem + OFF_OS);
    float2* seg_s  = (float2*)(smem + OFF_SEG);   // [chunk][half][hid]

    // ================= Phase 0 (once, all warps): bias + A fragments ======
    if (tid < 256) bias_s[tid] = bc[orig_oc(tid)];
    for (int combo = wid; combo < 192; combo += 12){
        const int mt = combo / 12, kt = combo % 12;
        const int r0 = mt * 16 + g;
        const int k0 = kt * 8;
        const int o0 = orig_oc(r0), o1 = orig_oc(r0 + 8);
        // m16n8k8 tf32 A-frag: a0=(g,tg) a1=(g+8,tg) a2=(g,tg+4) a3=(g+8,tg+4)
        uint4 av;
        av.x = to_tf32(Wc[o0 * KTOT + ck_of(k0 + tg)]);
        av.y = to_tf32(Wc[o1 * KTOT + ck_of(k0 + tg)]);
        av.z = to_tf32(Wc[o0 * KTOT + ck_of(k0 + tg + 4)]);
        av.w = to_tf32(Wc[o1 * KTOT + ck_of(k0 + tg + 4)]);
        *(uint4*)(smem + AFRAG_OFF(mt, kt, lane)) = av;
    }
    __syncthreads();

    if (wid < 8){
        // ===== A group: 2 warps/SMSP, per-half staggered handshake ========
        const int t  = wid >> 1;     // mt group: mt = t, 4+t, 8+t
        const int nh = wid & 1;      // nt = 4nh .. 4nh+3 (w 32*nh .. 32*nh+31)
        const int fb = nh ? 9 : 1;   // full barrier base for my half
        const int eb = nh ? 11 : 3;  // free barrier base for my half
        const float bi0 = bias_s[t*16 + g],        bi1 = bias_s[t*16 + g + 8];
        const float bf0 = bias_s[64 + t*16 + g],   bf1 = bias_s[64 + t*16 + g + 8];
        const float bg0 = bias_s[128 + t*16 + g],  bg1 = bias_s[128 + t*16 + g + 8];
        const float bo0 = bias_s[192 + t*16 + g],  bo1 = bias_s[192 + t*16 + g + 8];
        const int hid0 = t*16 + g, hid1 = t*16 + g + 8;
        int cnt = 0;

        for (int row = blockIdx.x; row < nrows; row += gridDim.x){
            const int h = row & (HDIM - 1);
            const int b = row >> 8;

            for (int n = 0; n < NCHUNK; n++){
                const int p = cnt & 1;
                bar_sync(fb + p, 256);           // my half of Bfrag[p] full

                float acc[3][4][4];
                #pragma unroll
                for (int m = 0; m < 3; m++)
                    #pragma unroll
                    for (int q = 0; q < 4; q++)
                        acc[m][q][0]=acc[m][q][1]=acc[m][q][2]=acc[m][q][3]=0.f;
                float oacc[4] = {0.f,0.f,0.f,0.f};

                #pragma unroll
                for (int kt = 0; kt < 12; kt++){
                    uint4 a0 = *(const uint4*)(smem + AFRAG_OFF(t,     kt, lane));
                    uint4 a1 = *(const uint4*)(smem + AFRAG_OFF(4 + t, kt, lane));
                    uint4 a2 = *(const uint4*)(smem + AFRAG_OFF(8 + t, kt, lane));
                    #pragma unroll
                    for (int q = 0; q < 4; q++){
                        uint2 bv = *(const uint2*)(smem + BOFF(p, kt, 4*nh + q, lane));
                        mma1688(acc[0][q], a0, bv);
                        mma1688(acc[1][q], a1, bv);
                        mma1688(acc[2][q], a2, bv);
                    }
                }
                if (n == NCHUNK - 1 && nh == 1){ // o gate: nt=7 lives in my half
                    #pragma unroll
                    for (int kt = 0; kt < 12; kt++){
                        uint4 ao = *(const uint4*)(smem + AFRAG_OFF(12 + t, kt, lane));
                        uint2 b7 = *(const uint2*)(smem + BOFF(p, kt, 7, lane));
                        mma1688(oacc, ao, b7);
                    }
                }
                bar_arrive(eb + p, 256);         // my half of Bfrag[p] free

                // ---- epilogue: activations + quad scan -> one (P,S) per hid
                float Ps0 = 1.f, Ss0 = 0.f, Ps1 = 1.f, Ss1 = 0.f;
                #pragma unroll
                for (int q = 0; q < 4; q++){
                    float i0 = sigmoid_f(acc[0][q][0] + bi0), i1 = sigmoid_f(acc[0][q][1] + bi0);
                    float f0 = sigmoid_f(acc[1][q][0] + bf0), f1 = sigmoid_f(acc[1][q][1] + bf0);
                    float g0 = tanh_f   (acc[2][q][0] + bg0), g1 = tanh_f   (acc[2][q][1] + bg0);
                    float P0 = f0 * f1;
                    float S0 = fmaf(f1, i0 * g0, i1 * g1);
                    float i2 = sigmoid_f(acc[0][q][2] + bi1), i3 = sigmoid_f(acc[0][q][3] + bi1);
                    float f2 = sigmoid_f(acc[1][q][2] + bf1), f3 = sigmoid_f(acc[1][q][3] + bf1);
                    float g2 = tanh_f   (acc[2][q][2] + bg1), g3 = tanh_f   (acc[2][q][3] + bg1);
                    float P1 = f2 * f3;
                    float S1 = fmaf(f3, i2 * g2, i3 * g3);
                    #pragma unroll
                    for (int d = 1; d <= 2; d <<= 1){
                        float Pu0 = __shfl_up_sync(0xffffffffu, P0, d, 4);
                        float Su0 = __shfl_up_sync(0xffffffffu, S0, d, 4);
                        float Pu1 = __shfl_up_sync(0xffffffffu, P1, d, 4);
                        float Su1 = __shfl_up_sync(0xffffffffu, S1, d, 4);
                        if (tg >= d){
                            S0 = fmaf(P0, Su0, S0);  P0 *= Pu0;
                            S1 = fmaf(P1, Su1, S1);  P1 *= Pu1;
                        }
                    }
                    if (tg == 3){                 // compose octet into segment
                        Ss0 = fmaf(P0, Ss0, S0);  Ps0 *= P0;
                        Ss1 = fmaf(P1, Ss1, S1);  Ps1 *= P1;
                    }
                }
                if (tg == 3){                     // publish segment (deferred compose)
                    seg_s[(n*2 + nh)*64 + hid0] = make_float2(Ps0, Ss0);
                    seg_s[(n*2 + nh)*64 + hid1] = make_float2(Ps1, Ss1);
                    if (n == NCHUNK - 1 && nh == 1){   // sigma(o) at w=255
                        o_s[hid0] = sigmoid_f(oacc[1] + bo0);
                        o_s[hid1] = sigmoid_f(oacc[3] + bo1);
                    }
                }
                cnt++;
            }

            // ---- row tail: fold 8 segments in w order, then write h
            bar_sync(7, 256);                    // all segments + o_s visible
            if (tid < 64){
                const int hid = tid;
                float c = 0.f;
                #pragma unroll
                for (int s = 0; s < 2*NCHUNK; s++){
                    float2 ps = seg_s[s*64 + hid];
                    c = fmaf(ps.x, c, ps.y);
                }
                h_s[hid] = o_s[hid] * tanh_f(c);
            }
            bar_sync(8, 256);                    // h_s visible to all A threads
            // broadcast write out[b][hid][h][0..255]  (256 A threads)
            #pragma unroll
            for (int j = 0; j < 16; j++){
                int idx = j * 256 + tid;         // 0..4095 float4 slots
                int hid = idx >> 6, w4 = idx & 63;
                float v = h_s[hid];
                float4 vv = make_float4(v, v, v, v);
                *(float4*)(out + (((size_t)b * 64 + hid) * HDIM + h) * WDIM + w4 * 4) = vv;
            }
        }
    } else {
        // ==== B group: stage x + build Bfrag half0 then half1 (producer) ==
        const int bw = wid - 8;                  // 0..3 -> nt bw (half0), bw+4 (half1)
        const int tl = tid - 256;                // 0..127
        int cnt = 0;

        for (int row = blockIdx.x; row < nrows; row += gridDim.x){
            const int h = row & (HDIM - 1);
            const int b = row >> 8;

            for (int n = 0; n < NCHUNK; n++){
                const int p = cnt & 1;
                const int w0g = n * WT;

                // ---- stage x chunk -> scr (coalesced float4, halo zero)
                #pragma unroll
                for (int it = 0; it < 12; it++){
                    int idx = tl + it * 128;     // 0..1535 float4 slots
                    int r  = idx >> 4;           // k index 0..95
                    int c4 = idx & 15;
                    int hh = h + (r >> 5) - 1;
                    float4 v = make_float4(0.f, 0.f, 0.f, 0.f);
                    if (hh >= 0 && hh < HDIM)
                        v = *(const float4*)(x + (((size_t)b * C_IN + (r & 31)) * HDIM + hh) * WDIM + w0g + c4 * 4);
                    *(float4*)(scr + r * SPITCH + c4 * 4) = v;
                }
                bar_sync(5, 128);                // B-internal: scr ready

                // ---- half 0 (nt = bw)
                if (cnt >= 2) bar_sync(3 + p, 256);   // E0[p]: freed by A nh=0
                {
                    const int nt = bw;
                    const int w  = nt * 8 + g;
                    #pragma unroll
                    for (int kt = 0; kt < 12; kt++){
                        const int k0 = kt * 8;
                        // m16n8k8 tf32 B-frag: b0=(tg, g)  b1=(tg+4, g)
                        uint2 bv;
                        bv.x = to_tf32(scr[(k0 + tg)     * SPITCH + w]);
                        bv.y = to_tf32(scr[(k0 + tg + 4) * SPITCH + w]);
                        *(uint2*)(smem + BOFF(p, kt, nt, lane)) = bv;
                    }
                }
                bar_arrive(1 + p, 256);          // F0[p] full

                // ---- half 1 (nt = bw+4)
                if (cnt >= 2) bar_sync(11 + p, 256);  // E1[p]: freed by A nh=1
                {
                    const int nt = bw + 4;
                    const int w  = nt * 8 + g;
                    #pragma unroll
                    for (int kt = 0; kt < 12; kt++){
                        const int k0 = kt * 8;
                        uint2 bv;
                        bv.x = to_tf32(scr[(k0 + tg)     * SPITCH + w]);
                        bv.y = to_tf32(scr[(k0 + tg + 4) * SPITCH + w]);
                        *(uint2*)(smem + BOFF(p, kt, nt, lane)) = bv;
                    }
                }
                bar_arrive(9 + p, 256);          // F1[p] full
                bar_sync(6, 128);                // B-internal: scr free
                cnt++;
            }
        }
    }
}

extern "C" void kernel_launch(void* const* d_in, const int* in_sizes, int n_in,
                              void* d_out, int out_size)
{
    const float* x  = (const float*)d_in[0];
    const float* Wc = (const float*)d_in[1];
    const float* bc = (const float*)d_in[2];
    float* out = (float*)d_out;

    const int B = in_sizes[0] / (C_IN * HDIM * WDIM);
    const int nrows = B * HDIM;

    static bool attr_done = false;
    if (!attr_done){
        cudaFuncSetAttribute(rowlstm_tf32,
                             cudaFuncAttributeMaxDynamicSharedMemorySize,
                             SMEM_BYTES);
        attr_done = true;
    }

    int grid = 148;
    if (nrows < grid) grid = nrows;
    rowlstm_tf32<<<grid, NTHREADS, SMEM_BYTES>>>(x, Wc, bc, out, nrows);
}